// round 15
// baseline (speedup 1.0000x reference)
#include <cuda_runtime.h>
#include <math.h>

#define N_NODES 4096
#define KDIM    512
#define D_H     64
#define HEADS   8
#define MAXD    192
#define CH      64
#define KSPLIT  16
#define KS      32
#define BM      64
#define ROWBLKS (N_NODES / BM)              // 64
#define GEMM_BLOCKS (ROWBLKS * KSPLIT)      // 1024
#define CSR_BLOCKS  1024

typedef unsigned long long ull;

// ---------------- packed f32x2 helpers (Blackwell) ----------------
__device__ __forceinline__ ull pack2(float a) {
    ull r;
    asm("mov.b64 %0, {%1, %1};" : "=l"(r) : "f"(a));
    return r;
}
__device__ __forceinline__ void fma2(ull& d, ull a, ull b) {
    asm("fma.rn.f32x2 %0, %1, %2, %0;" : "+l"(d) : "l"(a), "l"(b));
}
__device__ __forceinline__ void add2(ull& d, ull a) {
    asm("add.rn.f32x2 %0, %0, %1;" : "+l"(d) : "l"(a));
}
__device__ __forceinline__ void unpack2(ull v, float& lo, float& hi) {
    asm("mov.b64 {%0, %1}, %2;" : "=f"(lo), "=f"(hi) : "l"(v));
}

// ---------------- scratch ----------------
__device__ float g_x [N_NODES * D_H];
__device__ float g_el[N_NODES * HEADS];
__device__ float g_er[N_NODES * HEADS];
__device__ float g_h1[N_NODES * D_H * HEADS];
__device__ float g_h2[N_NODES * D_H * HEADS];
__device__ float g_part[KSPLIT * N_NODES * D_H];   // 16 MB
__device__ int   g_cols[N_NODES * MAXD];
__device__ int   g_deg [N_NODES];

// ---- split-K GEMM (BM=64, 8x4 thread tile) + fused CSR build --------------
// gemm blocks [0, GEMM_BLOCKS): rowblock = bx>>4 (64 rows), split = bx&15 (K=32).
// csr blocks  [GEMM_BLOCKS, ...): 4 warps, warp per adjacency row (layer 0 only).
__global__ __launch_bounds__(128, 6) void gemm_csr_kernel(const float* __restrict__ adj,
                                                          const float* __restrict__ A,
                                                          const float* __restrict__ B) {
    if (blockIdx.x >= GEMM_BLOCKS) {
        int warp = (blockIdx.x - GEMM_BLOCKS) * 4 + (threadIdx.x >> 5);
        int lane = threadIdx.x & 31;
        const float4* a = reinterpret_cast<const float4*>(adj + (size_t)warp * N_NODES);
        int* outc = g_cols + warp * MAXD;
        int base = 0;
        for (int j0 = 0; j0 < N_NODES; j0 += 128) {
            float4 v = a[(j0 >> 2) + lane];
            float vv[4] = {v.x, v.y, v.z, v.w};
            #pragma unroll
            for (int c = 0; c < 4; c++) {
                unsigned m = __ballot_sync(0xffffffffu, vv[c] != 0.0f);
                if (vv[c] != 0.0f) {
                    int pos = base + __popc(m & ((1u << lane) - 1u));
                    if (pos < MAXD) outc[pos] = j0 + lane * 4 + c;
                }
                base += __popc(m);
            }
        }
        if (lane == 0) g_deg[warp] = base < MAXD ? base : MAXD;
        return;
    }

    // ------- GEMM partial: 64 rows x 64 cols, K slice 32, 8x4 thread tile --
    __shared__ float AsT[32][72];   // [k][row], rows XOR-swizzled in groups of 4
    __shared__ float Bs[32][64];
    int tid = threadIdx.x;
    int tx = tid & 15, ty = tid >> 4;           // ty 0..7 -> rows ty*8 .. ty*8+7
    int rowBase = (blockIdx.x >> 4) * BM;
    int k0      = (blockIdx.x & 15) * KS;

    // stage A [64 rows x 32 k], transposed + swizzled: 4 float4/thread
    #pragma unroll
    for (int s = 0; s < 4; s++) {
        int idx = tid + 128 * s;
        int row = idx >> 3;                      // 0..63
        int kk  = (idx & 7) << 2;                // 0..28
        float4 v = *reinterpret_cast<const float4*>(
            A + (size_t)(rowBase + row) * KDIM + k0 + kk);
        float av[4] = {v.x, v.y, v.z, v.w};
        #pragma unroll
        for (int i = 0; i < 4; i++) {
            int k = kk + i;
            AsT[k][row ^ (((k >> 3) & 3) << 2)] = av[i];
        }
    }
    // stage B [32 k x 64 n]: 4 float4/thread
    #pragma unroll
    for (int s = 0; s < 4; s++) {
        int idx = tid + 128 * s;
        *reinterpret_cast<float4*>(&Bs[idx >> 4][(idx & 15) << 2]) =
            *reinterpret_cast<const float4*>(B + (size_t)(k0 + (idx >> 4)) * 64 + ((idx & 15) << 2));
    }
    __syncthreads();

    ull acc[8][2] = {{0,0},{0,0},{0,0},{0,0},{0,0},{0,0},{0,0},{0,0}};
    #pragma unroll
    for (int k = 0; k < KS; k++) {
        int x = ((k >> 3) & 3) << 2;
        float4 a0 = *reinterpret_cast<const float4*>(&AsT[k][(ty * 8) ^ x]);
        float4 a1 = *reinterpret_cast<const float4*>(&AsT[k][(ty * 8 + 4) ^ x]);
        ulonglong2 bb = *reinterpret_cast<const ulonglong2*>(&Bs[k][tx * 4]);
        ull p0 = pack2(a0.x), p1 = pack2(a0.y), p2 = pack2(a0.z), p3 = pack2(a0.w);
        ull p4 = pack2(a1.x), p5 = pack2(a1.y), p6 = pack2(a1.z), p7 = pack2(a1.w);
        fma2(acc[0][0], p0, bb.x); fma2(acc[0][1], p0, bb.y);
        fma2(acc[1][0], p1, bb.x); fma2(acc[1][1], p1, bb.y);
        fma2(acc[2][0], p2, bb.x); fma2(acc[2][1], p2, bb.y);
        fma2(acc[3][0], p3, bb.x); fma2(acc[3][1], p3, bb.y);
        fma2(acc[4][0], p4, bb.x); fma2(acc[4][1], p4, bb.y);
        fma2(acc[5][0], p5, bb.x); fma2(acc[5][1], p5, bb.y);
        fma2(acc[6][0], p6, bb.x); fma2(acc[6][1], p6, bb.y);
        fma2(acc[7][0], p7, bb.x); fma2(acc[7][1], p7, bb.y);
    }

    float* P = g_part + (size_t)(blockIdx.x & 15) * (N_NODES * D_H);
    #pragma unroll
    for (int i = 0; i < 8; i++) {
        int r = rowBase + ty * 8 + i;
        ulonglong2 v; v.x = acc[i][0]; v.y = acc[i][1];
        *reinterpret_cast<ulonglong2*>(P + (size_t)r * 64 + tx * 4) = v;
    }
}

// ---- reduce 16 split-K partials (fixed order) + el/er projection ----------
// 256 blocks x 256 threads; block handles 16 rows; thread handles one float4.
__global__ __launch_bounds__(256) void reduce_proj_kernel(const float* __restrict__ al,
                                                          const float* __restrict__ ar,
                                                          float* __restrict__ X, int H) {
    __shared__ float sC[1024];       // 16 rows x 64
    __shared__ float sAl[512];
    __shared__ float sAr[512];
    int tid = threadIdx.x;
    int rowBase = blockIdx.x * 16;
    size_t off4 = (size_t)rowBase * 16 + tid;          // float4 index in [N*16)
    const float4* p = reinterpret_cast<const float4*>(g_part) + off4;
    const size_t SZ4 = (size_t)N_NODES * 16;           // float4s per partial

    float4 v[16];
    #pragma unroll
    for (int s = 0; s < 16; s++) v[s] = p[s * SZ4];
    #pragma unroll
    for (int st = 8; st >= 1; st >>= 1) {
        #pragma unroll
        for (int s = 0; s < st; s++) {
            v[s].x += v[s + st].x; v[s].y += v[s + st].y;
            v[s].z += v[s + st].z; v[s].w += v[s + st].w;
        }
    }
    reinterpret_cast<float4*>(X)[off4] = v[0];
    *reinterpret_cast<float4*>(&sC[tid * 4]) = v[0];

    for (int idx = tid; idx < 64 * H; idx += 256) {
        sAl[idx] = al[idx];
        sAr[idx] = ar[idx];
    }
    __syncthreads();
    if (tid < 16 * H) {
        int r = (H == 8) ? (tid >> 3) : tid;
        int h = (H == 8) ? (tid & 7)  : 0;
        float sl = 0.f, sr = 0.f;
        #pragma unroll
        for (int d = 0; d < 64; d++) {
            float cv = sC[r * 64 + d];
            sl += cv * sAl[d * H + h];
            sr += cv * sAr[d * H + h];
        }
        g_el[(rowBase + r) * H + h] = sl;
        g_er[(rowBase + r) * H + h] = sr;
    }
}

// ---------------- 8-head aggregation: WARP per node, 4 nodes/block ---------
__global__ __launch_bounds__(128) void agg8_kernel(const float* __restrict__ bias,
                                                   float* __restrict__ out, int act) {
    int w    = threadIdx.x >> 5;
    int lane = threadIdx.x & 31;
    int i    = blockIdx.x * 4 + w;
    int h    = lane & 7;
    int qg   = lane >> 3;

    __shared__ int s_cols[4][CH];
    __shared__ ull s_w[4][CH][HEADS];

    int deg = g_deg[i];
    const int* cols = g_cols + (size_t)i * MAXD;
    float elh = g_el[i * HEADS + h];
    const float* xbase = g_x + qg * 16;

    ull acc[8] = {0,0,0,0,0,0,0,0};
    ull sw2 = 0ull;

    for (int j0 = 0; j0 < deg; j0 += CH) {
        int cl = min(CH, deg - j0);
        if (lane < cl)      s_cols[w][lane]      = cols[j0 + lane];
        if (lane + 32 < cl) s_cols[w][lane + 32] = cols[j0 + lane + 32];
        __syncwarp();
        for (int idx = lane; idx < cl * 8; idx += 32) {
            int jj = idx >> 3;
            float s = elh + g_er[s_cols[w][jj] * HEADS + h];
            s = (s >= 0.f) ? s : 0.2f * s;
            s_w[w][jj][h] = pack2(__expf(s));
        }
        __syncwarp();
        #pragma unroll 2
        for (int jj = 0; jj < cl; jj++) {
            ull pw = s_w[w][jj][h];
            const float* xr = xbase + (size_t)s_cols[w][jj] * D_H;
            ulonglong2 x0 = *reinterpret_cast<const ulonglong2*>(xr);
            ulonglong2 x1 = *reinterpret_cast<const ulonglong2*>(xr + 4);
            ulonglong2 x2 = *reinterpret_cast<const ulonglong2*>(xr + 8);
            ulonglong2 x3 = *reinterpret_cast<const ulonglong2*>(xr + 12);
            fma2(acc[0], pw, x0.x); fma2(acc[1], pw, x0.y);
            fma2(acc[2], pw, x1.x); fma2(acc[3], pw, x1.y);
            fma2(acc[4], pw, x2.x); fma2(acc[5], pw, x2.y);
            fma2(acc[6], pw, x3.x); fma2(acc[7], pw, x3.y);
            add2(sw2, pw);
        }
        __syncwarp();
    }

    float sw, dmy;
    unpack2(sw2, sw, dmy);
    float inv = 1.0f / fmaxf(sw, 1e-12f);
    float* o = out + (size_t)i * (HEADS * D_H) + h * D_H + qg * 16;
    const float* bq = bias + qg * 16;
    #pragma unroll
    for (int t4 = 0; t4 < 4; t4++) {
        float v0, v1, v2, v3;
        unpack2(acc[t4*2],   v0, v1);
        unpack2(acc[t4*2+1], v2, v3);
        v0 = v0 * inv + bq[t4*4+0];
        v1 = v1 * inv + bq[t4*4+1];
        v2 = v2 * inv + bq[t4*4+2];
        v3 = v3 * inv + bq[t4*4+3];
        if (act) {
            v0 = (v0 > 0.f) ? v0 : expm1f(v0);
            v1 = (v1 > 0.f) ? v1 : expm1f(v1);
            v2 = (v2 > 0.f) ? v2 : expm1f(v2);
            v3 = (v3 > 0.f) ? v3 : expm1f(v3);
        }
        *reinterpret_cast<float4*>(o + t4 * 4) = make_float4(v0, v1, v2, v3);
    }
}

// ---------------- 1-head aggregation: WARP per node, 4 nodes/block ---------
__global__ __launch_bounds__(128) void agg1_kernel(const float* __restrict__ bias,
                                                   float* __restrict__ out) {
    int w    = threadIdx.x >> 5;
    int lane = threadIdx.x & 31;
    int i    = blockIdx.x * 4 + w;

    __shared__ int s_cols[4][CH];
    __shared__ ull s_w[4][CH];

    int deg = g_deg[i];
    const int* cols = g_cols + (size_t)i * MAXD;
    float eli = g_el[i];
    const float* xbase = g_x + lane * 2;

    ull acc = 0ull, sw2 = 0ull;

    for (int j0 = 0; j0 < deg; j0 += CH) {
        int cl = min(CH, deg - j0);
        if (lane < cl) {
            int c = cols[j0 + lane];
            s_cols[w][lane] = c;
            float s = eli + g_er[c];
            s = (s >= 0.f) ? s : 0.2f * s;
            s_w[w][lane] = pack2(__expf(s));
        }
        if (lane + 32 < cl) {
            int c = cols[j0 + lane + 32];
            s_cols[w][lane + 32] = c;
            float s = eli + g_er[c];
            s = (s >= 0.f) ? s : 0.2f * s;
            s_w[w][lane + 32] = pack2(__expf(s));
        }
        __syncwarp();
        #pragma unroll 4
        for (int jj = 0; jj < cl; jj++) {
            ull pw = s_w[w][jj];
            ull xv = *reinterpret_cast<const ull*>(xbase + (size_t)s_cols[w][jj] * D_H);
            fma2(acc, pw, xv);
            add2(sw2, pw);
        }
        __syncwarp();
    }

    float sw, dmy;
    unpack2(sw2, sw, dmy);
    float inv = 1.0f / fmaxf(sw, 1e-12f);
    float v0, v1;
    unpack2(acc, v0, v1);
    v0 = v0 * inv + bias[lane * 2];
    v1 = v1 * inv + bias[lane * 2 + 1];
    *reinterpret_cast<float2*>(out + (size_t)i * D_H + lane * 2) = make_float2(v0, v1);
}

// ---------------- launch ---------------------------------------------------
extern "C" void kernel_launch(void* const* d_in, const int* in_sizes, int n_in,
                              void* d_out, int out_size) {
    const float* adj  = (const float*)d_in[0];
    const float* feat = (const float*)d_in[1];
    const float* W0   = (const float*)d_in[2];
    const float* al0  = (const float*)d_in[3];
    const float* ar0  = (const float*)d_in[4];
    const float* b0   = (const float*)d_in[5];
    const float* W1   = (const float*)d_in[6];
    const float* al1  = (const float*)d_in[7];
    const float* ar1  = (const float*)d_in[8];
    const float* b1   = (const float*)d_in[9];
    const float* W2   = (const float*)d_in[10];
    const float* al2  = (const float*)d_in[11];
    const float* ar2  = (const float*)d_in[12];
    const float* b2   = (const float*)d_in[13];
    float* out = (float*)d_out;

    float *x, *h1, *h2;
    cudaGetSymbolAddress((void**)&x,  g_x);
    cudaGetSymbolAddress((void**)&h1, g_h1);
    cudaGetSymbolAddress((void**)&h2, g_h2);

    // layer 0 (CSR build fused into the GEMM launch as extra blocks)
    gemm_csr_kernel<<<GEMM_BLOCKS + CSR_BLOCKS, 128>>>(adj, feat, W0);
    reduce_proj_kernel<<<N_NODES / 16, 256>>>(al0, ar0, x, HEADS);
    agg8_kernel<<<N_NODES / 4, 128>>>(b0, h1, 1);

    // layer 1
    gemm_csr_kernel<<<GEMM_BLOCKS, 128>>>(adj, h1, W1);
    reduce_proj_kernel<<<N_NODES / 16, 256>>>(al1, ar1, x, HEADS);
    agg8_kernel<<<N_NODES / 4, 128>>>(b1, h2, 1);

    // layer 2
    gemm_csr_kernel<<<GEMM_BLOCKS, 128>>>(adj, h2, W2);
    reduce_proj_kernel<<<N_NODES / 16, 256>>>(al2, ar2, x, 1);
    agg1_kernel<<<N_NODES / 4, 128>>>(b2, out);
}

// round 16
// speedup vs baseline: 1.0598x; 1.0598x over previous
#include <cuda_runtime.h>
#include <math.h>

#define N_NODES 4096
#define KDIM    512
#define D_H     64
#define HEADS   8
#define MAXD    192
#define CH      64
#define KSPLIT  16
#define KS      32
#define BM      32
#define ROWBLKS (N_NODES / BM)              // 128
#define GEMM_BLOCKS (ROWBLKS * KSPLIT)      // 2048
#define CSR_BLOCKS  1024
#define RED_BLOCKS  (N_NODES / 16)          // 256

typedef unsigned long long ull;

// ---------------- packed f32x2 helpers (Blackwell) ----------------
__device__ __forceinline__ ull pack2(float a) {
    ull r;
    asm("mov.b64 %0, {%1, %1};" : "=l"(r) : "f"(a));
    return r;
}
__device__ __forceinline__ void fma2(ull& d, ull a, ull b) {
    asm("fma.rn.f32x2 %0, %1, %2, %0;" : "+l"(d) : "l"(a), "l"(b));
}
__device__ __forceinline__ void add2(ull& d, ull a) {
    asm("add.rn.f32x2 %0, %0, %1;" : "+l"(d) : "l"(a));
}
__device__ __forceinline__ void unpack2(ull v, float& lo, float& hi) {
    asm("mov.b64 {%0, %1}, %2;" : "=f"(lo), "=f"(hi) : "l"(v));
}
__device__ __forceinline__ float4 f4add(float4 a, float4 b) {
    return make_float4(a.x + b.x, a.y + b.y, a.z + b.z, a.w + b.w);
}

// ---------------- scratch ----------------
__device__ float g_x [N_NODES * D_H];
__device__ float g_el[N_NODES * HEADS];
__device__ float g_er[N_NODES * HEADS];
__device__ float g_h1[N_NODES * D_H * HEADS];
__device__ float g_h2[N_NODES * D_H * HEADS];
__device__ float g_part[KSPLIT * N_NODES * D_H];   // 16 MB
__device__ int   g_cols[N_NODES * MAXD];
__device__ int   g_deg [N_NODES];
__device__ unsigned g_cnt[ROWBLKS];   // zero at start; reset by agg1 after layer 2

// ---- fused launch: split-K GEMM + (CSR layer 0) + gated reduce/proj tail --
// blocks [0, GEMM_BLOCKS): gemm partial. rowblock = bx>>4 (32 rows), split = bx&15.
// blocks [GEMM_BLOCKS, +csrN): CSR build (layer 0 only).
// blocks [GEMM_BLOCKS+csrN, +RED_BLOCKS): reduce 16 partials + el/er proj (16 rows).
__global__ __launch_bounds__(128, 8)
void gemm_fused_kernel(const float* __restrict__ adj,
                       const float* __restrict__ A,
                       const float* __restrict__ B,
                       const float* __restrict__ al,
                       const float* __restrict__ ar,
                       float* __restrict__ X, int H, int csrN, unsigned target) {
    __shared__ float sPool[3200];   // 12.8 KB, aliased per branch
    int tid = threadIdx.x;
    int bx  = blockIdx.x;

    if (bx >= GEMM_BLOCKS + csrN) {
        // ---------------- reduce + projection tail blocks ------------------
        int rblk    = bx - GEMM_BLOCKS - csrN;
        int rowBase = rblk * 16;
        int rb      = rowBase >> 5;
        if (tid == 0) {
            while (*(volatile unsigned*)&g_cnt[rb] < target) __nanosleep(64);
        }
        __syncthreads();

        float* sC  = sPool;          // 1024
        float* sAl = sPool + 1024;   // 512
        float* sAr = sPool + 1536;   // 512
        const size_t SZ4 = (size_t)N_NODES * 16;
        #pragma unroll
        for (int s = 0; s < 2; s++) {
            int idx = tid + 128 * s;                        // 0..255
            size_t off4 = (size_t)rowBase * 16 + idx;
            const float4* p = reinterpret_cast<const float4*>(g_part) + off4;
            float4 v[8];
            #pragma unroll
            for (int s2 = 0; s2 < 8; s2++) v[s2] = __ldcg(p + s2 * SZ4);
            float4 lo = f4add(f4add(f4add(v[0], v[1]), f4add(v[2], v[3])),
                              f4add(f4add(v[4], v[5]), f4add(v[6], v[7])));
            #pragma unroll
            for (int s2 = 0; s2 < 8; s2++) v[s2] = __ldcg(p + (8 + s2) * SZ4);
            float4 hi = f4add(f4add(f4add(v[0], v[1]), f4add(v[2], v[3])),
                              f4add(f4add(v[4], v[5]), f4add(v[6], v[7])));
            float4 r = f4add(lo, hi);
            reinterpret_cast<float4*>(X)[off4] = r;
            *reinterpret_cast<float4*>(&sC[idx * 4]) = r;
        }
        for (int idx = tid; idx < 64 * H; idx += 128) {
            sAl[idx] = al[idx];
            sAr[idx] = ar[idx];
        }
        __syncthreads();
        if (tid < 16 * H) {
            int r = (H == 8) ? (tid >> 3) : tid;
            int h = (H == 8) ? (tid & 7)  : 0;
            float sl = 0.f, sr = 0.f;
            #pragma unroll
            for (int d = 0; d < 64; d++) {
                float cv = sC[r * 64 + d];
                sl += cv * sAl[d * H + h];
                sr += cv * sAr[d * H + h];
            }
            g_el[(rowBase + r) * H + h] = sl;
            g_er[(rowBase + r) * H + h] = sr;
        }
        return;
    }

    if (bx >= GEMM_BLOCKS) {
        // ---------------- CSR build (layer 0 only) -------------------------
        int warp = (bx - GEMM_BLOCKS) * 4 + (tid >> 5);
        int lane = tid & 31;
        const float4* a = reinterpret_cast<const float4*>(adj + (size_t)warp * N_NODES);
        int* outc = g_cols + warp * MAXD;
        int base = 0;
        for (int j0 = 0; j0 < N_NODES; j0 += 128) {
            float4 v = a[(j0 >> 2) + lane];
            float vv[4] = {v.x, v.y, v.z, v.w};
            #pragma unroll
            for (int c = 0; c < 4; c++) {
                unsigned m = __ballot_sync(0xffffffffu, vv[c] != 0.0f);
                if (vv[c] != 0.0f) {
                    int pos = base + __popc(m & ((1u << lane) - 1u));
                    if (pos < MAXD) outc[pos] = j0 + lane * 4 + c;
                }
                base += __popc(m);
            }
        }
        if (lane == 0) g_deg[warp] = base < MAXD ? base : MAXD;
        return;
    }

    // ------- GEMM partial: 32 rows x 64 cols, K slice 32, 4x4 thread tile --
    float* AsT = sPool;           // [k][row pad 36]: 32*36 = 1152
    float* Bs  = sPool + 1152;    // [k][n]: 32*64 = 2048
    int tx = tid & 15, ty = tid >> 4;
    int rb      = bx >> 4;
    int rowBase = rb * BM;
    int k0      = (bx & 15) * KS;

    #pragma unroll
    for (int s = 0; s < 2; s++) {
        int idx = tid + 128 * s;
        int row = idx >> 3;
        int kk  = (idx & 7) << 2;
        float4 v = *reinterpret_cast<const float4*>(
            A + (size_t)(rowBase + row) * KDIM + k0 + kk);
        float av[4] = {v.x, v.y, v.z, v.w};
        #pragma unroll
        for (int i = 0; i < 4; i++) {
            int k = kk + i;
            AsT[k * 36 + (row ^ (((k >> 3) & 3) << 2))] = av[i];
        }
    }
    #pragma unroll
    for (int s = 0; s < 4; s++) {
        int idx = tid + 128 * s;
        *reinterpret_cast<float4*>(&Bs[(idx >> 4) * 64 + ((idx & 15) << 2)]) =
            *reinterpret_cast<const float4*>(B + (size_t)(k0 + (idx >> 4)) * 64 + ((idx & 15) << 2));
    }
    __syncthreads();

    ull acc[4][2] = {{0,0},{0,0},{0,0},{0,0}};
    #pragma unroll
    for (int k = 0; k < KS; k++) {
        int sr = (ty ^ ((k >> 3) & 3)) << 2;
        float4 av = *reinterpret_cast<const float4*>(&AsT[k * 36 + sr]);
        ulonglong2 bb = *reinterpret_cast<const ulonglong2*>(&Bs[k * 64 + tx * 4]);
        ull pa0 = pack2(av.x), pa1 = pack2(av.y), pa2 = pack2(av.z), pa3 = pack2(av.w);
        fma2(acc[0][0], pa0, bb.x); fma2(acc[0][1], pa0, bb.y);
        fma2(acc[1][0], pa1, bb.x); fma2(acc[1][1], pa1, bb.y);
        fma2(acc[2][0], pa2, bb.x); fma2(acc[2][1], pa2, bb.y);
        fma2(acc[3][0], pa3, bb.x); fma2(acc[3][1], pa3, bb.y);
    }

    float* P = g_part + (size_t)(bx & 15) * (N_NODES * D_H);
    #pragma unroll
    for (int i = 0; i < 4; i++) {
        int r = rowBase + ty * 4 + i;
        ulonglong2 v; v.x = acc[i][0]; v.y = acc[i][1];
        *reinterpret_cast<ulonglong2*>(P + (size_t)r * 64 + tx * 4) = v;
    }
    __syncthreads();
    if (tid == 0) {
        __threadfence();
        atomicAdd(&g_cnt[rb], 1u);
    }
}

// ---------------- 8-head aggregation: WARP per node, 4 nodes/block ---------
__global__ __launch_bounds__(128) void agg8_kernel(const float* __restrict__ bias,
                                                   float* __restrict__ out, int act) {
    int w    = threadIdx.x >> 5;
    int lane = threadIdx.x & 31;
    int i    = blockIdx.x * 4 + w;
    int h    = lane & 7;
    int qg   = lane >> 3;

    __shared__ int s_cols[4][CH];
    __shared__ ull s_w[4][CH][HEADS];

    int deg = g_deg[i];
    const int* cols = g_cols + (size_t)i * MAXD;
    float elh = g_el[i * HEADS + h];
    const float* xbase = g_x + qg * 16;

    ull acc[8] = {0,0,0,0,0,0,0,0};
    ull sw2 = 0ull;

    for (int j0 = 0; j0 < deg; j0 += CH) {
        int cl = min(CH, deg - j0);
        if (lane < cl)      s_cols[w][lane]      = cols[j0 + lane];
        if (lane + 32 < cl) s_cols[w][lane + 32] = cols[j0 + lane + 32];
        __syncwarp();
        for (int idx = lane; idx < cl * 8; idx += 32) {
            int jj = idx >> 3;
            float s = elh + g_er[s_cols[w][jj] * HEADS + h];
            s = (s >= 0.f) ? s : 0.2f * s;
            s_w[w][jj][h] = pack2(__expf(s));
        }
        __syncwarp();
        #pragma unroll 2
        for (int jj = 0; jj < cl; jj++) {
            ull pw = s_w[w][jj][h];
            const float* xr = xbase + (size_t)s_cols[w][jj] * D_H;
            ulonglong2 x0 = *reinterpret_cast<const ulonglong2*>(xr);
            ulonglong2 x1 = *reinterpret_cast<const ulonglong2*>(xr + 4);
            ulonglong2 x2 = *reinterpret_cast<const ulonglong2*>(xr + 8);
            ulonglong2 x3 = *reinterpret_cast<const ulonglong2*>(xr + 12);
            fma2(acc[0], pw, x0.x); fma2(acc[1], pw, x0.y);
            fma2(acc[2], pw, x1.x); fma2(acc[3], pw, x1.y);
            fma2(acc[4], pw, x2.x); fma2(acc[5], pw, x2.y);
            fma2(acc[6], pw, x3.x); fma2(acc[7], pw, x3.y);
            add2(sw2, pw);
        }
        __syncwarp();
    }

    float sw, dmy;
    unpack2(sw2, sw, dmy);
    float inv = 1.0f / fmaxf(sw, 1e-12f);
    float* o = out + (size_t)i * (HEADS * D_H) + h * D_H + qg * 16;
    const float* bq = bias + qg * 16;
    #pragma unroll
    for (int t4 = 0; t4 < 4; t4++) {
        float v0, v1, v2, v3;
        unpack2(acc[t4*2],   v0, v1);
        unpack2(acc[t4*2+1], v2, v3);
        v0 = v0 * inv + bq[t4*4+0];
        v1 = v1 * inv + bq[t4*4+1];
        v2 = v2 * inv + bq[t4*4+2];
        v3 = v3 * inv + bq[t4*4+3];
        if (act) {
            v0 = (v0 > 0.f) ? v0 : expm1f(v0);
            v1 = (v1 > 0.f) ? v1 : expm1f(v1);
            v2 = (v2 > 0.f) ? v2 : expm1f(v2);
            v3 = (v3 > 0.f) ? v3 : expm1f(v3);
        }
        *reinterpret_cast<float4*>(o + t4 * 4) = make_float4(v0, v1, v2, v3);
    }
}

// ---------------- 1-head aggregation: WARP per node, 4 nodes/block ---------
// block 0 also resets the split-K counters for the next graph replay.
__global__ __launch_bounds__(128) void agg1_kernel(const float* __restrict__ bias,
                                                   float* __restrict__ out) {
    if (blockIdx.x == 0) g_cnt[threadIdx.x] = 0u;   // 128 counters, 128 threads

    int w    = threadIdx.x >> 5;
    int lane = threadIdx.x & 31;
    int i    = blockIdx.x * 4 + w;

    __shared__ int s_cols[4][CH];
    __shared__ ull s_w[4][CH];

    int deg = g_deg[i];
    const int* cols = g_cols + (size_t)i * MAXD;
    float eli = g_el[i];
    const float* xbase = g_x + lane * 2;

    ull acc = 0ull, sw2 = 0ull;

    for (int j0 = 0; j0 < deg; j0 += CH) {
        int cl = min(CH, deg - j0);
        if (lane < cl) {
            int c = cols[j0 + lane];
            s_cols[w][lane] = c;
            float s = eli + g_er[c];
            s = (s >= 0.f) ? s : 0.2f * s;
            s_w[w][lane] = pack2(__expf(s));
        }
        if (lane + 32 < cl) {
            int c = cols[j0 + lane + 32];
            s_cols[w][lane + 32] = c;
            float s = eli + g_er[c];
            s = (s >= 0.f) ? s : 0.2f * s;
            s_w[w][lane + 32] = pack2(__expf(s));
        }
        __syncwarp();
        #pragma unroll 4
        for (int jj = 0; jj < cl; jj++) {
            ull pw = s_w[w][jj];
            ull xv = *reinterpret_cast<const ull*>(xbase + (size_t)s_cols[w][jj] * D_H);
            fma2(acc, pw, xv);
            add2(sw2, pw);
        }
        __syncwarp();
    }

    float sw, dmy;
    unpack2(sw2, sw, dmy);
    float inv = 1.0f / fmaxf(sw, 1e-12f);
    float v0, v1;
    unpack2(acc, v0, v1);
    v0 = v0 * inv + bias[lane * 2];
    v1 = v1 * inv + bias[lane * 2 + 1];
    *reinterpret_cast<float2*>(out + (size_t)i * D_H + lane * 2) = make_float2(v0, v1);
}

// ---------------- launch ---------------------------------------------------
extern "C" void kernel_launch(void* const* d_in, const int* in_sizes, int n_in,
                              void* d_out, int out_size) {
    const float* adj  = (const float*)d_in[0];
    const float* feat = (const float*)d_in[1];
    const float* W0   = (const float*)d_in[2];
    const float* al0  = (const float*)d_in[3];
    const float* ar0  = (const float*)d_in[4];
    const float* b0   = (const float*)d_in[5];
    const float* W1   = (const float*)d_in[6];
    const float* al1  = (const float*)d_in[7];
    const float* ar1  = (const float*)d_in[8];
    const float* b1   = (const float*)d_in[9];
    const float* W2   = (const float*)d_in[10];
    const float* al2  = (const float*)d_in[11];
    const float* ar2  = (const float*)d_in[12];
    const float* b2   = (const float*)d_in[13];
    float* out = (float*)d_out;

    float *x, *h1, *h2;
    cudaGetSymbolAddress((void**)&x,  g_x);
    cudaGetSymbolAddress((void**)&h1, g_h1);
    cudaGetSymbolAddress((void**)&h2, g_h2);

    // layer 0: gemm + CSR + gated reduce/proj in one launch
    gemm_fused_kernel<<<GEMM_BLOCKS + CSR_BLOCKS + RED_BLOCKS, 128>>>(
        adj, feat, W0, al0, ar0, x, HEADS, CSR_BLOCKS, 16u);
    agg8_kernel<<<N_NODES / 4, 128>>>(b0, h1, 1);

    // layer 1
    gemm_fused_kernel<<<GEMM_BLOCKS + RED_BLOCKS, 128>>>(
        adj, h1, W1, al1, ar1, x, HEADS, 0, 32u);
    agg8_kernel<<<N_NODES / 4, 128>>>(b1, h2, 1);

    // layer 2
    gemm_fused_kernel<<<GEMM_BLOCKS + RED_BLOCKS, 128>>>(
        adj, h2, W2, al2, ar2, x, 1, 0, 48u);
    agg1_kernel<<<N_NODES / 4, 128>>>(b2, out);
}